// round 15
// baseline (speedup 1.0000x reference)
#include <cuda_runtime.h>
#include <cuda_bf16.h>
#include <cstdint>

using bf16 = __nv_bfloat16;
#define EPSF 1e-6f
static constexpr int BATCH=8, NSEQ=4096, DIM=1024, MTOT=BATCH*NSEQ, QKVW=3*DIM;

__device__ alignas(256) bf16 g_xh [(size_t)MTOT*DIM];
__device__ alignas(256) bf16 g_xl [(size_t)MTOT*DIM];
__device__ alignas(256) bf16 g_wqh[(size_t)QKVW*DIM];
__device__ alignas(256) bf16 g_wql[(size_t)QKVW*DIM];
__device__ alignas(256) bf16 g_woh[(size_t)DIM*DIM];
__device__ alignas(256) bf16 g_wol[(size_t)DIM*DIM];
__device__ alignas(256) bf16 g_qkvh[(size_t)MTOT*QKVW];
__device__ alignas(256) bf16 g_qkvl[(size_t)MTOT*QKVW];
__device__ alignas(256) bf16 g_kvh[(size_t)BATCH*DIM*DIM];
__device__ alignas(256) bf16 g_kvl[(size_t)BATCH*DIM*DIM];
__device__ alignas(256) bf16 g_ath[(size_t)MTOT*DIM];
__device__ alignas(256) bf16 g_atl[(size_t)MTOT*DIM];
__device__ float g_ksum[BATCH*DIM];
__device__ float g_z   [MTOT];

__device__ __forceinline__ uint32_t smem_u32(const void* p){
  uint32_t a; asm("{ .reg .u64 t; cvta.to.shared.u64 t, %1; cvt.u32.u64 %0, t; }":"=r"(a):"l"(p)); return a;
}
__device__ __forceinline__ void cpasync16(uint32_t dst, const void* src){
  asm volatile("cp.async.cg.shared.global [%0], [%1], 16;"::"r"(dst),"l"(src));
}
#define CP_COMMIT() asm volatile("cp.async.commit_group;":::"memory")
#define CP_WAIT1()  asm volatile("cp.async.wait_group 1;":::"memory")
#define CP_WAIT0()  asm volatile("cp.async.wait_group 0;":::"memory")
__device__ __forceinline__ void ldmx4(uint32_t* r, uint32_t addr){
  asm volatile("ldmatrix.sync.aligned.m8n8.x4.shared.b16 {%0,%1,%2,%3}, [%4];"
    :"=r"(r[0]),"=r"(r[1]),"=r"(r[2]),"=r"(r[3]):"r"(addr));
}
__device__ __forceinline__ void ldmx4t(uint32_t* r, uint32_t addr){
  asm volatile("ldmatrix.sync.aligned.m8n8.x4.trans.shared.b16 {%0,%1,%2,%3}, [%4];"
    :"=r"(r[0]),"=r"(r[1]),"=r"(r[2]),"=r"(r[3]):"r"(addr));
}
__device__ __forceinline__ void mma16816(float* c, const uint32_t* a, uint32_t b0, uint32_t b1){
  asm volatile("mma.sync.aligned.m16n8k16.row.col.f32.bf16.bf16.f32 "
    "{%0,%1,%2,%3},{%4,%5,%6,%7},{%8,%9},{%0,%1,%2,%3};"
    :"+f"(c[0]),"+f"(c[1]),"+f"(c[2]),"+f"(c[3])
    :"r"(a[0]),"r"(a[1]),"r"(a[2]),"r"(a[3]),"r"(b0),"r"(b1));
}
__device__ __forceinline__ uint32_t pack2h(float v0, float v1){
  union{uint32_t u; bf16 b[2];} H; H.b[0]=__float2bfloat16_rn(v0); H.b[1]=__float2bfloat16_rn(v1); return H.u;
}
__device__ __forceinline__ uint32_t pack2l(float v0, float v1){
  union{uint32_t u; bf16 b[2];} L;
  bf16 h0=__float2bfloat16_rn(v0), h1=__float2bfloat16_rn(v1);
  L.b[0]=__float2bfloat16_rn(v0-__bfloat162float(h0));
  L.b[1]=__float2bfloat16_rn(v1-__bfloat162float(h1));
  return L.u;
}

// BM=128, BN=256, BK=32. Stage 48KB: AH 0, AL 8K, BH 16K, BL 32K. 3 stages = 144KB.
// NT planes: A 128 rows x 64B, B 256 rows x 64B. TRANS: A 32 k-rows x 256B, B 32 k-rows x 512B.
static constexpr int STG = 49152, SMEM_DYN = 3*STG;

// C[M,N] = A[M,K]*B[N,K]^T (bf16x3 planes). TRANS: sources [K][*] contiguous, ldmatrix.trans.
// EPI: 0=relu+eps cols<2048 -> planes, 1=planes, 2=row-scale -> planes, 3=+bias -> fp32
template<bool TRANS, int EPI>
__global__ __launch_bounds__(256)
void hgemm(const bf16* __restrict__ Ah, const bf16* __restrict__ Al, long long ldA, long long bsA,
           const bf16* __restrict__ Bh, const bf16* __restrict__ Bl, long long ldB, long long bsB, int K,
           bf16* __restrict__ Ch, bf16* __restrict__ Cl, float* __restrict__ Cf, long long ldC, long long bsC,
           const float* __restrict__ rowScale, long long bsS,
           const float* __restrict__ bias)
{
  extern __shared__ char sm[];
  const uint32_t smb = smem_u32(sm);
  const int tid=threadIdx.x, wid=tid>>5, lane=tid&31, bz=blockIdx.z;
  Ah += (size_t)bz*bsA; Al += (size_t)bz*bsA;
  Bh += (size_t)bz*bsB; Bl += (size_t)bz*bsB;
  if(EPI==3) Cf += (size_t)bz*bsC; else { Ch += (size_t)bz*bsC; Cl += (size_t)bz*bsC; }
  if(EPI==2) rowScale += (size_t)bz*bsS;
  const int row0 = blockIdx.y*128, col0 = blockIdx.x*256;
  const int warpM = (wid>>2)*64, warpN = (wid&3)*64;
  const int NS = K>>5;

  float acc[4][8][4];
  #pragma unroll
  for(int i=0;i<4;i++)
    #pragma unroll
    for(int j=0;j<8;j++){ acc[i][j][0]=0.f;acc[i][j][1]=0.f;acc[i][j][2]=0.f;acc[i][j][3]=0.f; }

  auto issue = [&](int s, int st){
    const size_t kt = (size_t)s*32;
    const uint32_t bb = smb + st*STG;
    if(!TRANS){
      // A: 128 rows x 64B (4 x 16B cols), swizzle c ^ ((r>>1)&3); 512 chunks/plane
      #pragma unroll
      for(int i=0;i<2;i++){
        int p=tid+i*256, r=p>>2, c=p&3;
        uint32_t sw = (uint32_t)r*64 + (uint32_t)((c ^ ((r>>1)&3))<<4);
        const size_t ga = (size_t)(row0+r)*ldA + kt + c*8;
        cpasync16(bb +        sw, Ah + ga);
        cpasync16(bb + 8192 + sw, Al + ga);
      }
      // B: 256 rows x 64B; 1024 chunks/plane
      #pragma unroll
      for(int i=0;i<4;i++){
        int p=tid+i*256, r=p>>2, c=p&3;
        uint32_t sw = (uint32_t)r*64 + (uint32_t)((c ^ ((r>>1)&3))<<4);
        const size_t gb = (size_t)(col0+r)*ldB + kt + c*8;
        cpasync16(bb + 16384 + sw, Bh + gb);
        cpasync16(bb + 32768 + sw, Bl + gb);
      }
    } else {
      // A: 32 k-rows x 256B (16 x 16B cols), swizzle c ^ (r&7)
      #pragma unroll
      for(int i=0;i<2;i++){
        int p=tid+i*256, r=p>>4, c=p&15;
        uint32_t sw = (uint32_t)r*256 + (uint32_t)((c ^ (r&7))<<4);
        const size_t ga = (kt+r)*ldA + row0 + c*8;
        cpasync16(bb +        sw, Ah + ga);
        cpasync16(bb + 8192 + sw, Al + ga);
      }
      // B: 32 k-rows x 512B (32 x 16B cols), swizzle c ^ (r&7)
      #pragma unroll
      for(int i=0;i<4;i++){
        int p=tid+i*256, r=p>>5, c=p&31;
        uint32_t sw = (uint32_t)r*512 + (uint32_t)((c ^ (r&7))<<4);
        const size_t gb = (kt+r)*ldB + col0 + c*8;
        cpasync16(bb + 16384 + sw, Bh + gb);
        cpasync16(bb + 32768 + sw, Bl + gb);
      }
    }
    CP_COMMIT();
  };

  const uint32_t ln7 = (uint32_t)(lane&7), ln16 = (uint32_t)(lane>>4);
  const uint32_t rowsel = ln7 + (uint32_t)(((lane>>3)&1)*8);
  const uint32_t fsw = (uint32_t)((lane>>1)&3);   // NT 64B-row ldmatrix swizzle term
  auto domma = [&](int st){
    const uint32_t bb = smb + st*STG;
    #pragma unroll
    for(int kb=0;kb<2;kb++){
      const uint32_t cl = (uint32_t)(2*kb + ln16);
      uint32_t bH[8][2], bL[8][2];
      #pragma unroll
      for(int np=0;np<4;np++){
        uint32_t ad;
        if(!TRANS){
          ad = bb + 16384 + (warpN + np*16 + rowsel)*64 + ((cl ^ fsw)<<4);
        } else {
          uint32_t rk = (uint32_t)(kb*16) + ln16*8 + ln7;
          uint32_t c16 = ((uint32_t)((warpN+np*16)>>3) + ((lane>>3)&1)) ^ ln7;
          ad = bb + 16384 + rk*512 + (c16<<4);
        }
        uint32_t r[4];
        if(!TRANS) ldmx4(r, ad); else ldmx4t(r, ad);
        bH[np*2][0]=r[0]; bH[np*2+1][0]=r[1]; bH[np*2][1]=r[2]; bH[np*2+1][1]=r[3];
        if(!TRANS) ldmx4(r, ad+16384); else ldmx4t(r, ad+16384);
        bL[np*2][0]=r[0]; bL[np*2+1][0]=r[1]; bL[np*2][1]=r[2]; bL[np*2+1][1]=r[3];
      }
      #pragma unroll
      for(int mi=0;mi<4;mi++){
        uint32_t ad;
        if(!TRANS){
          ad = bb + (warpM + mi*16 + rowsel)*64 + ((cl ^ fsw)<<4);
        } else {
          uint32_t rk = (uint32_t)(kb*16) + ln16*8 + ln7;
          uint32_t c16 = ((uint32_t)((warpM+mi*16)>>3) + ((lane>>3)&1)) ^ ln7;
          ad = bb + rk*256 + (c16<<4);
        }
        uint32_t aH[4], aL[4];
        if(!TRANS){ ldmx4(aH, ad); ldmx4(aL, ad+8192); }
        else      { ldmx4t(aH, ad); ldmx4t(aL, ad+8192); }
        #pragma unroll
        for(int ni=0;ni<8;ni++) mma16816(acc[mi][ni], aH, bH[ni][0], bH[ni][1]);
        #pragma unroll
        for(int ni=0;ni<8;ni++) mma16816(acc[mi][ni], aH, bL[ni][0], bL[ni][1]);
        #pragma unroll
        for(int ni=0;ni<8;ni++) mma16816(acc[mi][ni], aL, bH[ni][0], bH[ni][1]);
      }
    }
  };

  // 3-stage ring, single barrier per iteration:
  //   wait(stage s) ; sync (all warps done with stage s-1) ; issue s+2 -> stage (s-1)%3 ; mma stage s
  issue(0,0);
  if(NS>1) issue(1,1);
  for(int s=0;s<NS;++s){
    if(s < NS-1) CP_WAIT1(); else CP_WAIT0();
    __syncthreads();
    if(s+2<NS) issue(s+2, (s+2)%3);
    domma(s%3);
  }

  #pragma unroll
  for(int mi=0;mi<4;mi++){
    const int r0 = row0 + warpM + mi*16 + (lane>>2);
    float s0=1.f, s1=1.f;
    if(EPI==2){ s0=rowScale[r0]; s1=rowScale[r0+8]; }
    #pragma unroll
    for(int ni=0;ni<8;ni++){
      const int c = col0 + warpN + ni*8 + 2*(lane&3);
      float v0=acc[mi][ni][0], v1=acc[mi][ni][1], v2=acc[mi][ni][2], v3=acc[mi][ni][3];
      if(EPI==0 && c<2048){
        v0=fmaxf(v0,0.f)+EPSF; v1=fmaxf(v1,0.f)+EPSF;
        v2=fmaxf(v2,0.f)+EPSF; v3=fmaxf(v3,0.f)+EPSF;
      }
      if(EPI==2){ v0*=s0; v1*=s0; v2*=s1; v3*=s1; }
      if(EPI==3){
        float b0=bias[c], b1=bias[c+1];
        *(float2*)(Cf + (size_t)r0*ldC + c)     = make_float2(v0+b0, v1+b1);
        *(float2*)(Cf + (size_t)(r0+8)*ldC + c) = make_float2(v2+b0, v3+b1);
      } else {
        *(uint32_t*)(Ch + (size_t)r0*ldC + c)     = pack2h(v0,v1);
        *(uint32_t*)(Cl + (size_t)r0*ldC + c)     = pack2l(v0,v1);
        *(uint32_t*)(Ch + (size_t)(r0+8)*ldC + c) = pack2h(v2,v3);
        *(uint32_t*)(Cl + (size_t)(r0+8)*ldC + c) = pack2l(v2,v3);
      }
    }
  }
}

__global__ void split_kernel(const float* __restrict__ src, bf16* __restrict__ h, bf16* __restrict__ l){
  size_t i = ((size_t)blockIdx.x*256 + threadIdx.x)*4;
  float4 v = *(const float4*)(src+i);
  float f[4]={v.x,v.y,v.z,v.w};
  union{uint2 u; bf16 b[4];} H,L;
  #pragma unroll
  for(int k=0;k<4;k++){ bf16 hh=__float2bfloat16_rn(f[k]); H.b[k]=hh; L.b[k]=__float2bfloat16_rn(f[k]-__bfloat162float(hh)); }
  *(uint2*)(h+i)=H.u; *(uint2*)(l+i)=L.u;
}
__global__ void ksum_zero(float* ks){ ks[blockIdx.x*256+threadIdx.x]=0.f; }
__global__ void ksum_kernel(const bf16* __restrict__ qh, const bf16* __restrict__ ql, float* __restrict__ ks){
  int d=blockIdx.x*256+threadIdx.x, b=blockIdx.y, nz=blockIdx.z;
  const size_t base = (size_t)b*NSEQ*QKVW + (size_t)nz*512*QKVW + DIM + d;
  float s=0.f;
  #pragma unroll 8
  for(int n=0;n<512;n++){
    size_t o = base + (size_t)n*QKVW;
    s += __bfloat162float(qh[o]) + __bfloat162float(ql[o]);
  }
  atomicAdd(&ks[b*DIM+d], s);
}
__global__ void z_kernel(const bf16* __restrict__ qh, const bf16* __restrict__ ql,
                         const float* __restrict__ ks, float* __restrict__ z){
  int row=blockIdx.x*8+(threadIdx.x>>5), lane=threadIdx.x&31, b=row>>12;
  const bf16* qhp = qh + (size_t)row*QKVW;
  const bf16* qlp = ql + (size_t)row*QKVW;
  const float* kp = ks + b*DIM;
  float s=0.f;
  #pragma unroll 8
  for(int i=lane;i<DIM;i+=32)
    s += (__bfloat162float(qhp[i])+__bfloat162float(qlp[i]))*kp[i];
  #pragma unroll
  for(int o=16;o>0;o>>=1) s += __shfl_xor_sync(0xFFFFFFFFu,s,o);
  if(lane==0) z[row]=1.f/(s+EPSF);
}

extern "C" void kernel_launch(void* const* d_in, const int* in_sizes, int n_in,
                              void* d_out, int out_size)
{
  const float* x    = (const float*)d_in[0];
  const float* Wqkv = (const float*)d_in[1];
  const float* Wout = (const float*)d_in[2];
  const float* bout = (const float*)d_in[3];
  float* out = (float*)d_out;
  bf16 *xh,*xl,*wqh,*wql,*woh,*wol,*qkvh,*qkvl,*kvh,*kvl,*ath,*atl;
  float *ksum,*z;
  cudaGetSymbolAddress((void**)&xh,g_xh);   cudaGetSymbolAddress((void**)&xl,g_xl);
  cudaGetSymbolAddress((void**)&wqh,g_wqh); cudaGetSymbolAddress((void**)&wql,g_wql);
  cudaGetSymbolAddress((void**)&woh,g_woh); cudaGetSymbolAddress((void**)&wol,g_wol);
  cudaGetSymbolAddress((void**)&qkvh,g_qkvh); cudaGetSymbolAddress((void**)&qkvl,g_qkvl);
  cudaGetSymbolAddress((void**)&kvh,g_kvh); cudaGetSymbolAddress((void**)&kvl,g_kvl);
  cudaGetSymbolAddress((void**)&ath,g_ath); cudaGetSymbolAddress((void**)&atl,g_atl);
  cudaGetSymbolAddress((void**)&ksum,g_ksum); cudaGetSymbolAddress((void**)&z,g_z);
  cudaFuncSetAttribute(hgemm<false,0>, cudaFuncAttributeMaxDynamicSharedMemorySize, SMEM_DYN);
  cudaFuncSetAttribute(hgemm<true ,1>, cudaFuncAttributeMaxDynamicSharedMemorySize, SMEM_DYN);
  cudaFuncSetAttribute(hgemm<false,2>, cudaFuncAttributeMaxDynamicSharedMemorySize, SMEM_DYN);
  cudaFuncSetAttribute(hgemm<false,3>, cudaFuncAttributeMaxDynamicSharedMemorySize, SMEM_DYN);
  const long long sQ=(long long)NSEQ*QKVW, sKV=(long long)DIM*DIM, sA=(long long)NSEQ*DIM;

  split_kernel<<<(MTOT*(size_t)DIM)/1024, 256>>>(x, xh, xl);
  split_kernel<<<((size_t)QKVW*DIM)/1024, 256>>>(Wqkv, wqh, wql);
  split_kernel<<<((size_t)DIM*DIM)/1024, 256>>>(Wout, woh, wol);
  // 1) qkv = x @ Wqkv^T, relu+eps on q,k  -> planes
  hgemm<false,0><<<dim3(QKVW/256, MTOT/128, 1),256,SMEM_DYN>>>(
      xh, xl, DIM,0, wqh, wql, DIM,0, DIM, qkvh, qkvl, nullptr, QKVW,0, nullptr,0, nullptr);
  // 2) ksum
  ksum_zero<<<32,256>>>(ksum);
  ksum_kernel<<<dim3(DIM/256,BATCH,8),256>>>(qkvh, qkvl, ksum);
  // 3) kvT[b,e,d] = sum_n V[n,e]K[n,d]  (ldmatrix.trans path) -> planes
  hgemm<true,1><<<dim3(DIM/256, DIM/128, BATCH),256,SMEM_DYN>>>(
      qkvh+2*DIM, qkvl+2*DIM, QKVW, sQ, qkvh+DIM, qkvl+DIM, QKVW, sQ, NSEQ,
      kvh, kvl, nullptr, DIM, sKV, nullptr,0, nullptr);
  // 4) z
  z_kernel<<<MTOT/8,256>>>(qkvh, qkvl, ksum, z);
  // 5) attn[n,e] = z[n] * Q[n,:]·kvT[e,:] -> planes
  hgemm<false,2><<<dim3(DIM/256, NSEQ/128, BATCH),256,SMEM_DYN>>>(
      qkvh, qkvl, QKVW, sQ, kvh, kvl, DIM, sKV, DIM,
      ath, atl, nullptr, DIM, sA, z, NSEQ, nullptr);
  // 6) out = attn @ Wout^T + b  -> fp32
  hgemm<false,3><<<dim3(DIM/256, MTOT/128, 1),256,SMEM_DYN>>>(
      ath, atl, DIM,0, woh, wol, DIM,0, DIM,
      nullptr, nullptr, out, DIM,0, nullptr,0, bout);
}

// round 16
// speedup vs baseline: 1.0650x; 1.0650x over previous
#include <cuda_runtime.h>
#include <cuda_bf16.h>
#include <cstdint>

using bf16 = __nv_bfloat16;
#define EPSF 1e-6f
static constexpr int BATCH=8, NSEQ=4096, DIM=1024, MTOT=BATCH*NSEQ, QKVW=3*DIM;

__device__ alignas(256) bf16 g_xh [(size_t)MTOT*DIM];
__device__ alignas(256) bf16 g_xl [(size_t)MTOT*DIM];
__device__ alignas(256) bf16 g_wqh[(size_t)QKVW*DIM];
__device__ alignas(256) bf16 g_wql[(size_t)QKVW*DIM];
__device__ alignas(256) bf16 g_woh[(size_t)DIM*DIM];
__device__ alignas(256) bf16 g_wol[(size_t)DIM*DIM];
__device__ alignas(256) bf16 g_qkvh[(size_t)MTOT*QKVW];
__device__ alignas(256) bf16 g_qkvl[(size_t)MTOT*QKVW];
__device__ alignas(256) bf16 g_kvh[(size_t)BATCH*DIM*DIM];
__device__ alignas(256) bf16 g_kvl[(size_t)BATCH*DIM*DIM];
__device__ alignas(256) bf16 g_ath[(size_t)MTOT*DIM];
__device__ alignas(256) bf16 g_atl[(size_t)MTOT*DIM];
__device__ float g_ksum[BATCH*DIM];
__device__ float g_z   [MTOT];

__device__ __forceinline__ uint32_t smem_u32(const void* p){
  uint32_t a; asm("{ .reg .u64 t; cvta.to.shared.u64 t, %1; cvt.u32.u64 %0, t; }":"=r"(a):"l"(p)); return a;
}
__device__ __forceinline__ void cpasync16(uint32_t dst, const void* src){
  asm volatile("cp.async.cg.shared.global [%0], [%1], 16;"::"r"(dst),"l"(src));
}
#define CP_COMMIT() asm volatile("cp.async.commit_group;":::"memory")
#define CP_WAIT1()  asm volatile("cp.async.wait_group 1;":::"memory")
#define CP_WAIT0()  asm volatile("cp.async.wait_group 0;":::"memory")
__device__ __forceinline__ void ldmx4(uint32_t* r, uint32_t addr){
  asm volatile("ldmatrix.sync.aligned.m8n8.x4.shared.b16 {%0,%1,%2,%3}, [%4];"
    :"=r"(r[0]),"=r"(r[1]),"=r"(r[2]),"=r"(r[3]):"r"(addr));
}
__device__ __forceinline__ void ldmx4t(uint32_t* r, uint32_t addr){
  asm volatile("ldmatrix.sync.aligned.m8n8.x4.trans.shared.b16 {%0,%1,%2,%3}, [%4];"
    :"=r"(r[0]),"=r"(r[1]),"=r"(r[2]),"=r"(r[3]):"r"(addr));
}
__device__ __forceinline__ void mma16816(float* c, const uint32_t* a, uint32_t b0, uint32_t b1){
  asm volatile("mma.sync.aligned.m16n8k16.row.col.f32.bf16.bf16.f32 "
    "{%0,%1,%2,%3},{%4,%5,%6,%7},{%8,%9},{%0,%1,%2,%3};"
    :"+f"(c[0]),"+f"(c[1]),"+f"(c[2]),"+f"(c[3])
    :"r"(a[0]),"r"(a[1]),"r"(a[2]),"r"(a[3]),"r"(b0),"r"(b1));
}
__device__ __forceinline__ uint32_t pack2h(float v0, float v1){
  union{uint32_t u; bf16 b[2];} H; H.b[0]=__float2bfloat16_rn(v0); H.b[1]=__float2bfloat16_rn(v1); return H.u;
}
__device__ __forceinline__ uint32_t pack2l(float v0, float v1){
  union{uint32_t u; bf16 b[2];} L;
  bf16 h0=__float2bfloat16_rn(v0), h1=__float2bfloat16_rn(v1);
  L.b[0]=__float2bfloat16_rn(v0-__bfloat162float(h0));
  L.b[1]=__float2bfloat16_rn(v1-__bfloat162float(h1));
  return L.u;
}

// BM=128, BN=128, BK=64. Stage 64KB: AH 0, AL 16K, BH 32K, BL 48K (128B rows NT; 256B rows TRANS).
// 3 stages = 192KB. 256 compute threads (8 warps, 64x32 tiles) + 64 producer threads.
static constexpr int STG = 65536, SMEM_DYN = 3*STG;
static constexpr int THREADS = 320;

// C[M,N] = A[M,K]*B[N,K]^T (bf16x3 planes). TRANS: sources [K][*] contiguous, ldmatrix.trans.
// EPI: 0=relu+eps cols<2048 -> planes, 1=planes, 2=row-scale -> planes, 3=+bias -> fp32
template<bool TRANS, int EPI>
__global__ __launch_bounds__(THREADS,1)
void hgemm(const bf16* __restrict__ Ah, const bf16* __restrict__ Al, long long ldA, long long bsA,
           const bf16* __restrict__ Bh, const bf16* __restrict__ Bl, long long ldB, long long bsB, int K,
           bf16* __restrict__ Ch, bf16* __restrict__ Cl, float* __restrict__ Cf, long long ldC, long long bsC,
           const float* __restrict__ rowScale, long long bsS,
           const float* __restrict__ bias)
{
  extern __shared__ char sm[];
  const uint32_t smb = smem_u32(sm);
  const int tid=threadIdx.x, wid=tid>>5, lane=tid&31, bz=blockIdx.z;
  Ah += (size_t)bz*bsA; Al += (size_t)bz*bsA;
  Bh += (size_t)bz*bsB; Bl += (size_t)bz*bsB;
  if(EPI==3) Cf += (size_t)bz*bsC; else { Ch += (size_t)bz*bsC; Cl += (size_t)bz*bsC; }
  if(EPI==2) rowScale += (size_t)bz*bsS;
  const int row0 = blockIdx.y*128, col0 = blockIdx.x*128;
  const int warpM = ((wid>>2)&1)*64, warpN = (wid&3)*32;
  const int NS = K>>6;
  const bool producer = (wid >= 8);
  const int p0 = tid - 256;               // 0..63 for producers

  // ---- producer: issue one 64KB stage (64 cp.async per thread) ----
  auto issue = [&](int s, int st){
    const size_t kt = (size_t)s*64;
    const uint32_t bb = smb + st*STG;
    if(!TRANS){
      #pragma unroll
      for(int i=0;i<16;i++){
        int idx=p0+i*64, r=idx>>3, c=idx&7;       // 128 rows x 8 cols
        uint32_t sw = (uint32_t)r*128 + (uint32_t)((c ^ (r&7))<<4);
        const size_t ga = (size_t)(row0+r)*ldA + kt + c*8;
        const size_t gb = (size_t)(col0+r)*ldB + kt + c*8;
        cpasync16(bb +         sw, Ah + ga);
        cpasync16(bb + 16384 + sw, Al + ga);
        cpasync16(bb + 32768 + sw, Bh + gb);
        cpasync16(bb + 49152 + sw, Bl + gb);
      }
    } else {
      #pragma unroll
      for(int i=0;i<16;i++){
        int idx=p0+i*64, r=idx>>4, c=idx&15;      // 64 k-rows x 16 cols (256B rows)
        uint32_t sw = (uint32_t)r*256 + (uint32_t)((c ^ (r&7))<<4);
        const size_t ga = (kt+r)*ldA + row0 + c*8;
        const size_t gb = (kt+r)*ldB + col0 + c*8;
        cpasync16(bb +         sw, Ah + ga);
        cpasync16(bb + 16384 + sw, Al + ga);
        cpasync16(bb + 32768 + sw, Bh + gb);
        cpasync16(bb + 49152 + sw, Bl + gb);
      }
    }
    CP_COMMIT();
  };

  float acc[4][4][4];
  #pragma unroll
  for(int i=0;i<4;i++)
    #pragma unroll
    for(int j=0;j<4;j++){ acc[i][j][0]=0.f;acc[i][j][1]=0.f;acc[i][j][2]=0.f;acc[i][j][3]=0.f; }

  const uint32_t ln7 = (uint32_t)(lane&7), ln16 = (uint32_t)(lane>>4);
  const uint32_t rowsel = ln7 + (uint32_t)(((lane>>3)&1)*8);
  auto domma = [&](int st){
    const uint32_t bb = smb + st*STG;
    #pragma unroll
    for(int kb=0;kb<4;kb++){
      const uint32_t cl = (uint32_t)(2*kb + ln16);
      uint32_t bH[4][2], bL[4][2];
      #pragma unroll
      for(int np=0;np<2;np++){
        uint32_t ad;
        if(!TRANS){
          ad = bb + 32768 + (warpN + np*16 + rowsel)*128 + ((cl ^ ln7)<<4);
        } else {
          uint32_t rk = (uint32_t)(kb*16) + ln16*8 + ln7;
          uint32_t c16 = ((uint32_t)((warpN+np*16)>>3) + ((lane>>3)&1)) ^ ln7;
          ad = bb + 32768 + rk*256 + (c16<<4);
        }
        uint32_t r[4];
        if(!TRANS) ldmx4(r, ad); else ldmx4t(r, ad);
        bH[np*2][0]=r[0]; bH[np*2+1][0]=r[1]; bH[np*2][1]=r[2]; bH[np*2+1][1]=r[3];
        if(!TRANS) ldmx4(r, ad+16384); else ldmx4t(r, ad+16384);
        bL[np*2][0]=r[0]; bL[np*2+1][0]=r[1]; bL[np*2][1]=r[2]; bL[np*2+1][1]=r[3];
      }
      #pragma unroll
      for(int mi=0;mi<4;mi++){
        uint32_t ad;
        if(!TRANS){
          ad = bb + (warpM + mi*16 + rowsel)*128 + ((cl ^ ln7)<<4);
        } else {
          uint32_t rk = (uint32_t)(kb*16) + ln16*8 + ln7;
          uint32_t c16 = ((uint32_t)((warpM+mi*16)>>3) + ((lane>>3)&1)) ^ ln7;
          ad = bb + rk*256 + (c16<<4);
        }
        uint32_t aH[4], aL[4];
        if(!TRANS){ ldmx4(aH, ad); ldmx4(aL, ad+16384); }
        else      { ldmx4t(aH, ad); ldmx4t(aL, ad+16384); }
        #pragma unroll
        for(int ni=0;ni<4;ni++) mma16816(acc[mi][ni], aH, bH[ni][0], bH[ni][1]);
        #pragma unroll
        for(int ni=0;ni<4;ni++) mma16816(acc[mi][ni], aH, bL[ni][0], bL[ni][1]);
        #pragma unroll
        for(int ni=0;ni<4;ni++) mma16816(acc[mi][ni], aL, bH[ni][0], bH[ni][1]);
      }
    }
  };

  // ---- 3-stage producer/consumer pipeline, one barrier per k-chunk ----
  if(producer){ issue(0,0); if(NS>1) issue(1,1); }
  for(int s=0;s<NS;++s){
    if(producer){
      if(s < NS-2) CP_WAIT1(); else CP_WAIT0();   // stage s landed
    }
    __syncthreads();                               // all 320: stage s ready, stage (s-1)%3 drained
    if(producer){
      if(s+2<NS) issue(s+2, (s+2)%3);
    } else {
      domma(s%3);
    }
  }

  if(!producer){
    #pragma unroll
    for(int mi=0;mi<4;mi++){
      const int r0 = row0 + warpM + mi*16 + (lane>>2);
      float s0=1.f, s1=1.f;
      if(EPI==2){ s0=rowScale[r0]; s1=rowScale[r0+8]; }
      #pragma unroll
      for(int ni=0;ni<4;ni++){
        const int c = col0 + warpN + ni*8 + 2*(lane&3);
        float v0=acc[mi][ni][0], v1=acc[mi][ni][1], v2=acc[mi][ni][2], v3=acc[mi][ni][3];
        if(EPI==0 && c<2048){
          v0=fmaxf(v0,0.f)+EPSF; v1=fmaxf(v1,0.f)+EPSF;
          v2=fmaxf(v2,0.f)+EPSF; v3=fmaxf(v3,0.f)+EPSF;
        }
        if(EPI==2){ v0*=s0; v1*=s0; v2*=s1; v3*=s1; }
        if(EPI==3){
          float b0=bias[c], b1=bias[c+1];
          *(float2*)(Cf + (size_t)r0*ldC + c)     = make_float2(v0+b0, v1+b1);
          *(float2*)(Cf + (size_t)(r0+8)*ldC + c) = make_float2(v2+b0, v3+b1);
        } else {
          *(uint32_t*)(Ch + (size_t)r0*ldC + c)     = pack2h(v0,v1);
          *(uint32_t*)(Cl + (size_t)r0*ldC + c)     = pack2l(v0,v1);
          *(uint32_t*)(Ch + (size_t)(r0+8)*ldC + c) = pack2h(v2,v3);
          *(uint32_t*)(Cl + (size_t)(r0+8)*ldC + c) = pack2l(v2,v3);
        }
      }
    }
  }
}

__global__ void split_kernel(const float* __restrict__ src, bf16* __restrict__ h, bf16* __restrict__ l){
  size_t i = ((size_t)blockIdx.x*256 + threadIdx.x)*4;
  float4 v = *(const float4*)(src+i);
  float f[4]={v.x,v.y,v.z,v.w};
  union{uint2 u; bf16 b[4];} H,L;
  #pragma unroll
  for(int k=0;k<4;k++){ bf16 hh=__float2bfloat16_rn(f[k]); H.b[k]=hh; L.b[k]=__float2bfloat16_rn(f[k]-__bfloat162float(hh)); }
  *(uint2*)(h+i)=H.u; *(uint2*)(l+i)=L.u;
}
__global__ void ksum_zero(float* ks){ ks[blockIdx.x*256+threadIdx.x]=0.f; }
__global__ void ksum_kernel(const bf16* __restrict__ qh, const bf16* __restrict__ ql, float* __restrict__ ks){
  int d=blockIdx.x*256+threadIdx.x, b=blockIdx.y, nz=blockIdx.z;
  const size_t base = (size_t)b*NSEQ*QKVW + (size_t)nz*512*QKVW + DIM + d;
  float s=0.f;
  #pragma unroll 8
  for(int n=0;n<512;n++){
    size_t o = base + (size_t)n*QKVW;
    s += __bfloat162float(qh[o]) + __bfloat162float(ql[o]);
  }
  atomicAdd(&ks[b*DIM+d], s);
}
__global__ void z_kernel(const bf16* __restrict__ qh, const bf16* __restrict__ ql,
                         const float* __restrict__ ks, float* __restrict__ z){
  int row=blockIdx.x*8+(threadIdx.x>>5), lane=threadIdx.x&31, b=row>>12;
  const bf16* qhp = qh + (size_t)row*QKVW;
  const bf16* qlp = ql + (size_t)row*QKVW;
  const float* kp = ks + b*DIM;
  float s=0.f;
  #pragma unroll 8
  for(int i=lane;i<DIM;i+=32)
    s += (__bfloat162float(qhp[i])+__bfloat162float(qlp[i]))*kp[i];
  #pragma unroll
  for(int o=16;o>0;o>>=1) s += __shfl_xor_sync(0xFFFFFFFFu,s,o);
  if(lane==0) z[row]=1.f/(s+EPSF);
}

extern "C" void kernel_launch(void* const* d_in, const int* in_sizes, int n_in,
                              void* d_out, int out_size)
{
  const float* x    = (const float*)d_in[0];
  const float* Wqkv = (const float*)d_in[1];
  const float* Wout = (const float*)d_in[2];
  const float* bout = (const float*)d_in[3];
  float* out = (float*)d_out;
  bf16 *xh,*xl,*wqh,*wql,*woh,*wol,*qkvh,*qkvl,*kvh,*kvl,*ath,*atl;
  float *ksum,*z;
  cudaGetSymbolAddress((void**)&xh,g_xh);   cudaGetSymbolAddress((void**)&xl,g_xl);
  cudaGetSymbolAddress((void**)&wqh,g_wqh); cudaGetSymbolAddress((void**)&wql,g_wql);
  cudaGetSymbolAddress((void**)&woh,g_woh); cudaGetSymbolAddress((void**)&wol,g_wol);
  cudaGetSymbolAddress((void**)&qkvh,g_qkvh); cudaGetSymbolAddress((void**)&qkvl,g_qkvl);
  cudaGetSymbolAddress((void**)&kvh,g_kvh); cudaGetSymbolAddress((void**)&kvl,g_kvl);
  cudaGetSymbolAddress((void**)&ath,g_ath); cudaGetSymbolAddress((void**)&atl,g_atl);
  cudaGetSymbolAddress((void**)&ksum,g_ksum); cudaGetSymbolAddress((void**)&z,g_z);
  cudaFuncSetAttribute(hgemm<false,0>, cudaFuncAttributeMaxDynamicSharedMemorySize, SMEM_DYN);
  cudaFuncSetAttribute(hgemm<true ,1>, cudaFuncAttributeMaxDynamicSharedMemorySize, SMEM_DYN);
  cudaFuncSetAttribute(hgemm<false,2>, cudaFuncAttributeMaxDynamicSharedMemorySize, SMEM_DYN);
  cudaFuncSetAttribute(hgemm<false,3>, cudaFuncAttributeMaxDynamicSharedMemorySize, SMEM_DYN);
  const long long sQ=(long long)NSEQ*QKVW, sKV=(long long)DIM*DIM, sA=(long long)NSEQ*DIM;

  split_kernel<<<(MTOT*(size_t)DIM)/1024, 256>>>(x, xh, xl);
  split_kernel<<<((size_t)QKVW*DIM)/1024, 256>>>(Wqkv, wqh, wql);
  split_kernel<<<((size_t)DIM*DIM)/1024, 256>>>(Wout, woh, wol);
  // 1) qkv = x @ Wqkv^T, relu+eps on q,k  -> planes
  hgemm<false,0><<<dim3(QKVW/128, MTOT/128, 1),THREADS,SMEM_DYN>>>(
      xh, xl, DIM,0, wqh, wql, DIM,0, DIM, qkvh, qkvl, nullptr, QKVW,0, nullptr,0, nullptr);
  // 2) ksum
  ksum_zero<<<32,256>>>(ksum);
  ksum_kernel<<<dim3(DIM/256,BATCH,8),256>>>(qkvh, qkvl, ksum);
  // 3) kvT[b,e,d] = sum_n V[n,e]K[n,d]  (ldmatrix.trans path) -> planes
  hgemm<true,1><<<dim3(DIM/128, DIM/128, BATCH),THREADS,SMEM_DYN>>>(
      qkvh+2*DIM, qkvl+2*DIM, QKVW, sQ, qkvh+DIM, qkvl+DIM, QKVW, sQ, NSEQ,
      kvh, kvl, nullptr, DIM, sKV, nullptr,0, nullptr);
  // 4) z
  z_kernel<<<MTOT/8,256>>>(qkvh, qkvl, ksum, z);
  // 5) attn[n,e] = z[n] * Q[n,:]·kvT[e,:] -> planes
  hgemm<false,2><<<dim3(DIM/128, NSEQ/128, BATCH),THREADS,SMEM_DYN>>>(
      qkvh, qkvl, QKVW, sQ, kvh, kvl, DIM, sKV, DIM,
      ath, atl, nullptr, DIM, sA, z, NSEQ, nullptr);
  // 6) out = attn @ Wout^T + b  -> fp32
  hgemm<false,3><<<dim3(DIM/128, MTOT/128, 1),THREADS,SMEM_DYN>>>(
      ath, atl, DIM,0, woh, wol, DIM,0, DIM,
      nullptr, nullptr, out, DIM,0, nullptr,0, bout);
}

// round 17
// speedup vs baseline: 1.2087x; 1.1349x over previous
#include <cuda_runtime.h>
#include <cuda_bf16.h>
#include <cstdint>

using bf16 = __nv_bfloat16;
#define EPSF 1e-6f
static constexpr int BATCH=8, NSEQ=4096, DIM=1024, MTOT=BATCH*NSEQ, QKVW=3*DIM;

__device__ alignas(256) bf16 g_xh [(size_t)MTOT*DIM];
__device__ alignas(256) bf16 g_xl [(size_t)MTOT*DIM];
__device__ alignas(256) bf16 g_wqh[(size_t)QKVW*DIM];
__device__ alignas(256) bf16 g_wql[(size_t)QKVW*DIM];
__device__ alignas(256) bf16 g_woh[(size_t)DIM*DIM];
__device__ alignas(256) bf16 g_wol[(size_t)DIM*DIM];
__device__ alignas(256) bf16 g_qkvh[(size_t)MTOT*QKVW];
__device__ alignas(256) bf16 g_qkvl[(size_t)MTOT*QKVW];
__device__ alignas(256) bf16 g_kvh[(size_t)BATCH*DIM*DIM];   // kv[d,e] planes
__device__ alignas(256) bf16 g_kvl[(size_t)BATCH*DIM*DIM];
__device__ alignas(256) bf16 g_ph [(size_t)BATCH*DIM*DIM];   // P[f,d] planes
__device__ alignas(256) bf16 g_pl [(size_t)BATCH*DIM*DIM];
__device__ float g_ksum[BATCH*DIM];
__device__ float g_z   [MTOT];

__device__ __forceinline__ uint32_t smem_u32(const void* p){
  uint32_t a; asm("{ .reg .u64 t; cvta.to.shared.u64 t, %1; cvt.u32.u64 %0, t; }":"=r"(a):"l"(p)); return a;
}
__device__ __forceinline__ void cpasync16(uint32_t dst, const void* src){
  asm volatile("cp.async.cg.shared.global [%0], [%1], 16;"::"r"(dst),"l"(src));
}
#define CP_COMMIT() asm volatile("cp.async.commit_group;":::"memory")
#define CP_WAIT1()  asm volatile("cp.async.wait_group 1;":::"memory")
#define CP_WAIT0()  asm volatile("cp.async.wait_group 0;":::"memory")
__device__ __forceinline__ void ldmx4(uint32_t* r, uint32_t addr){
  asm volatile("ldmatrix.sync.aligned.m8n8.x4.shared.b16 {%0,%1,%2,%3}, [%4];"
    :"=r"(r[0]),"=r"(r[1]),"=r"(r[2]),"=r"(r[3]):"r"(addr));
}
__device__ __forceinline__ void ldmx4t(uint32_t* r, uint32_t addr){
  asm volatile("ldmatrix.sync.aligned.m8n8.x4.trans.shared.b16 {%0,%1,%2,%3}, [%4];"
    :"=r"(r[0]),"=r"(r[1]),"=r"(r[2]),"=r"(r[3]):"r"(addr));
}
__device__ __forceinline__ void mma16816(float* c, const uint32_t* a, uint32_t b0, uint32_t b1){
  asm volatile("mma.sync.aligned.m16n8k16.row.col.f32.bf16.bf16.f32 "
    "{%0,%1,%2,%3},{%4,%5,%6,%7},{%8,%9},{%0,%1,%2,%3};"
    :"+f"(c[0]),"+f"(c[1]),"+f"(c[2]),"+f"(c[3])
    :"r"(a[0]),"r"(a[1]),"r"(a[2]),"r"(a[3]),"r"(b0),"r"(b1));
}
__device__ __forceinline__ uint32_t pack2h(float v0, float v1){
  union{uint32_t u; bf16 b[2];} H; H.b[0]=__float2bfloat16_rn(v0); H.b[1]=__float2bfloat16_rn(v1); return H.u;
}
__device__ __forceinline__ uint32_t pack2l(float v0, float v1){
  union{uint32_t u; bf16 b[2];} L;
  bf16 h0=__float2bfloat16_rn(v0), h1=__float2bfloat16_rn(v1);
  L.b[0]=__float2bfloat16_rn(v0-__bfloat162float(h0));
  L.b[1]=__float2bfloat16_rn(v1-__bfloat162float(h1));
  return L.u;
}

// BM=128, BN=256, BK=64. Stage 96KB: AH 0, AL 16K, BH 32K, BL 64K. 2 stages = 192KB.
static constexpr int STG = 98304, SMEM_DYN = 2*STG;

// C[M,N] = A[M,K]*B[N,K]^T (bf16x3 planes). TRANS: sources [K][*] contiguous, ldmatrix.trans.
// EPI: 0=relu+eps cols<2048 -> planes, 1=planes, 4=row-scale+bias -> fp32
template<bool TRANS, int EPI>
__global__ __launch_bounds__(256)
void hgemm(const bf16* __restrict__ Ah, const bf16* __restrict__ Al, long long ldA, long long bsA,
           const bf16* __restrict__ Bh, const bf16* __restrict__ Bl, long long ldB, long long bsB, int K,
           bf16* __restrict__ Ch, bf16* __restrict__ Cl, float* __restrict__ Cf, long long ldC, long long bsC,
           const float* __restrict__ rowScale, long long bsS,
           const float* __restrict__ bias)
{
  extern __shared__ char sm[];
  const uint32_t smb = smem_u32(sm);
  const int tid=threadIdx.x, wid=tid>>5, lane=tid&31, bz=blockIdx.z;
  Ah += (size_t)bz*bsA; Al += (size_t)bz*bsA;
  Bh += (size_t)bz*bsB; Bl += (size_t)bz*bsB;
  if(EPI==4) Cf += (size_t)bz*bsC; else { Ch += (size_t)bz*bsC; Cl += (size_t)bz*bsC; }
  if(EPI==4) rowScale += (size_t)bz*bsS;
  const int row0 = blockIdx.y*128, col0 = blockIdx.x*256;
  const int warpM = (wid>>2)*64, warpN = (wid&3)*64;
  const int NS = K>>6;

  float acc[4][8][4];
  #pragma unroll
  for(int i=0;i<4;i++)
    #pragma unroll
    for(int j=0;j<8;j++){ acc[i][j][0]=0.f;acc[i][j][1]=0.f;acc[i][j][2]=0.f;acc[i][j][3]=0.f; }

  auto issue = [&](int s, int st){
    const size_t kt = (size_t)s*64;
    const uint32_t bb = smb + st*STG;
    if(!TRANS){
      #pragma unroll
      for(int i=0;i<4;i++){
        int p=tid+i*256, r=p>>3, c=p&7;
        uint32_t sw = (uint32_t)r*128 + (uint32_t)((c ^ (r&7))<<4);
        const size_t ga = (size_t)(row0+r)*ldA + kt + c*8;
        cpasync16(bb +         sw, Ah + ga);
        cpasync16(bb + 16384 + sw, Al + ga);
      }
      #pragma unroll
      for(int i=0;i<8;i++){
        int p=tid+i*256, r=p>>3, c=p&7;
        uint32_t sw = (uint32_t)r*128 + (uint32_t)((c ^ (r&7))<<4);
        const size_t gb = (size_t)(col0+r)*ldB + kt + c*8;
        cpasync16(bb + 32768 + sw, Bh + gb);
        cpasync16(bb + 65536 + sw, Bl + gb);
      }
    } else {
      #pragma unroll
      for(int i=0;i<4;i++){
        int p=tid+i*256, r=p>>4, c=p&15;
        uint32_t sw = (uint32_t)r*256 + (uint32_t)((c ^ (r&7))<<4);
        const size_t ga = (kt+r)*ldA + row0 + c*8;
        cpasync16(bb +         sw, Ah + ga);
        cpasync16(bb + 16384 + sw, Al + ga);
      }
      #pragma unroll
      for(int i=0;i<8;i++){
        int p=tid+i*256, r=p>>5, c=p&31;
        uint32_t sw = (uint32_t)r*512 + (uint32_t)((c ^ (r&7))<<4);
        const size_t gb = (kt+r)*ldB + col0 + c*8;
        cpasync16(bb + 32768 + sw, Bh + gb);
        cpasync16(bb + 65536 + sw, Bl + gb);
      }
    }
    CP_COMMIT();
  };

  const uint32_t ln7 = (uint32_t)(lane&7), ln16 = (uint32_t)(lane>>4);
  const uint32_t rowsel = ln7 + (uint32_t)(((lane>>3)&1)*8);
  auto domma = [&](int st){
    const uint32_t bb = smb + st*STG;
    #pragma unroll
    for(int kb=0;kb<4;kb++){
      uint32_t bH[8][2], bL[8][2];
      #pragma unroll
      for(int np=0;np<4;np++){
        uint32_t ad;
        if(!TRANS){
          uint32_t c16 = (uint32_t)(2*kb + ln16) ^ ln7;
          ad = bb + 32768 + (warpN + np*16 + rowsel)*128 + (c16<<4);
        } else {
          uint32_t rk = (uint32_t)(kb*16) + ln16*8 + ln7;
          uint32_t c16 = ((uint32_t)((warpN+np*16)>>3) + ((lane>>3)&1)) ^ ln7;
          ad = bb + 32768 + rk*512 + (c16<<4);
        }
        uint32_t r[4];
        if(!TRANS) ldmx4(r, ad); else ldmx4t(r, ad);
        bH[np*2][0]=r[0]; bH[np*2+1][0]=r[1]; bH[np*2][1]=r[2]; bH[np*2+1][1]=r[3];
        if(!TRANS) ldmx4(r, ad+32768); else ldmx4t(r, ad+32768);
        bL[np*2][0]=r[0]; bL[np*2+1][0]=r[1]; bL[np*2][1]=r[2]; bL[np*2+1][1]=r[3];
      }
      #pragma unroll
      for(int mi=0;mi<4;mi++){
        uint32_t ad;
        if(!TRANS){
          uint32_t c16 = (uint32_t)(2*kb + ln16) ^ ln7;
          ad = bb + (warpM + mi*16 + rowsel)*128 + (c16<<4);
        } else {
          uint32_t rk = (uint32_t)(kb*16) + ln16*8 + ln7;
          uint32_t c16 = ((uint32_t)((warpM+mi*16)>>3) + ((lane>>3)&1)) ^ ln7;
          ad = bb + rk*256 + (c16<<4);
        }
        uint32_t aH[4], aL[4];
        if(!TRANS){ ldmx4(aH, ad); ldmx4(aL, ad+16384); }
        else      { ldmx4t(aH, ad); ldmx4t(aL, ad+16384); }
        #pragma unroll
        for(int ni=0;ni<8;ni++) mma16816(acc[mi][ni], aH, bH[ni][0], bH[ni][1]);
        #pragma unroll
        for(int ni=0;ni<8;ni++) mma16816(acc[mi][ni], aH, bL[ni][0], bL[ni][1]);
        #pragma unroll
        for(int ni=0;ni<8;ni++) mma16816(acc[mi][ni], aL, bH[ni][0], bH[ni][1]);
      }
    }
  };

  issue(0,0);
  if(NS>1) issue(1,1);
  for(int s=0;s<NS;++s){
    if(s < NS-1) CP_WAIT1(); else CP_WAIT0();
    __syncthreads();
    domma(s&1);
    __syncthreads();
    if(s+2<NS) issue(s+2, s&1);
  }

  #pragma unroll
  for(int mi=0;mi<4;mi++){
    const int r0 = row0 + warpM + mi*16 + (lane>>2);
    float s0=1.f, s1=1.f;
    if(EPI==4){ s0=rowScale[r0]; s1=rowScale[r0+8]; }
    #pragma unroll
    for(int ni=0;ni<8;ni++){
      const int c = col0 + warpN + ni*8 + 2*(lane&3);
      float v0=acc[mi][ni][0], v1=acc[mi][ni][1], v2=acc[mi][ni][2], v3=acc[mi][ni][3];
      if(EPI==0 && c<2048){
        v0=fmaxf(v0,0.f)+EPSF; v1=fmaxf(v1,0.f)+EPSF;
        v2=fmaxf(v2,0.f)+EPSF; v3=fmaxf(v3,0.f)+EPSF;
      }
      if(EPI==4){
        float b0=bias[c], b1=bias[c+1];
        *(float2*)(Cf + (size_t)r0*ldC + c)     = make_float2(v0*s0+b0, v1*s0+b1);
        *(float2*)(Cf + (size_t)(r0+8)*ldC + c) = make_float2(v2*s1+b0, v3*s1+b1);
      } else {
        *(uint32_t*)(Ch + (size_t)r0*ldC + c)     = pack2h(v0,v1);
        *(uint32_t*)(Cl + (size_t)r0*ldC + c)     = pack2l(v0,v1);
        *(uint32_t*)(Ch + (size_t)(r0+8)*ldC + c) = pack2h(v2,v3);
        *(uint32_t*)(Cl + (size_t)(r0+8)*ldC + c) = pack2l(v2,v3);
      }
    }
  }
}

__global__ void split_kernel(const float* __restrict__ src, bf16* __restrict__ h, bf16* __restrict__ l){
  size_t i = ((size_t)blockIdx.x*256 + threadIdx.x)*4;
  float4 v = *(const float4*)(src+i);
  float f[4]={v.x,v.y,v.z,v.w};
  union{uint2 u; bf16 b[4];} H,L;
  #pragma unroll
  for(int k=0;k<4;k++){ bf16 hh=__float2bfloat16_rn(f[k]); H.b[k]=hh; L.b[k]=__float2bfloat16_rn(f[k]-__bfloat162float(hh)); }
  *(uint2*)(h+i)=H.u; *(uint2*)(l+i)=L.u;
}
__global__ void ksum_zero(float* ks){ ks[blockIdx.x*256+threadIdx.x]=0.f; }
__global__ void ksum_kernel(const bf16* __restrict__ qh, const bf16* __restrict__ ql, float* __restrict__ ks){
  int d=blockIdx.x*256+threadIdx.x, b=blockIdx.y, nz=blockIdx.z;
  const size_t base = (size_t)b*NSEQ*QKVW + (size_t)nz*512*QKVW + DIM + d;
  float s=0.f;
  #pragma unroll 8
  for(int n=0;n<512;n++){
    size_t o = base + (size_t)n*QKVW;
    s += __bfloat162float(qh[o]) + __bfloat162float(ql[o]);
  }
  atomicAdd(&ks[b*DIM+d], s);
}
__global__ void z_kernel(const bf16* __restrict__ qh, const bf16* __restrict__ ql,
                         const float* __restrict__ ks, float* __restrict__ z){
  int row=blockIdx.x*8+(threadIdx.x>>5), lane=threadIdx.x&31, b=row>>12;
  const bf16* qhp = qh + (size_t)row*QKVW;
  const bf16* qlp = ql + (size_t)row*QKVW;
  const float* kp = ks + b*DIM;
  float s=0.f;
  #pragma unroll 8
  for(int i=lane;i<DIM;i+=32)
    s += (__bfloat162float(qhp[i])+__bfloat162float(qlp[i]))*kp[i];
  #pragma unroll
  for(int o=16;o>0;o>>=1) s += __shfl_xor_sync(0xFFFFFFFFu,s,o);
  if(lane==0) z[row]=1.f/(s+EPSF);
}

extern "C" void kernel_launch(void* const* d_in, const int* in_sizes, int n_in,
                              void* d_out, int out_size)
{
  const float* x    = (const float*)d_in[0];
  const float* Wqkv = (const float*)d_in[1];
  const float* Wout = (const float*)d_in[2];
  const float* bout = (const float*)d_in[3];
  float* out = (float*)d_out;
  bf16 *xh,*xl,*wqh,*wql,*woh,*wol,*qkvh,*qkvl,*kvh,*kvl,*ph,*pl;
  float *ksum,*z;
  cudaGetSymbolAddress((void**)&xh,g_xh);   cudaGetSymbolAddress((void**)&xl,g_xl);
  cudaGetSymbolAddress((void**)&wqh,g_wqh); cudaGetSymbolAddress((void**)&wql,g_wql);
  cudaGetSymbolAddress((void**)&woh,g_woh); cudaGetSymbolAddress((void**)&wol,g_wol);
  cudaGetSymbolAddress((void**)&qkvh,g_qkvh); cudaGetSymbolAddress((void**)&qkvl,g_qkvl);
  cudaGetSymbolAddress((void**)&kvh,g_kvh); cudaGetSymbolAddress((void**)&kvl,g_kvl);
  cudaGetSymbolAddress((void**)&ph,g_ph);   cudaGetSymbolAddress((void**)&pl,g_pl);
  cudaGetSymbolAddress((void**)&ksum,g_ksum); cudaGetSymbolAddress((void**)&z,g_z);
  cudaFuncSetAttribute(hgemm<false,0>, cudaFuncAttributeMaxDynamicSharedMemorySize, SMEM_DYN);
  cudaFuncSetAttribute(hgemm<true ,1>, cudaFuncAttributeMaxDynamicSharedMemorySize, SMEM_DYN);
  cudaFuncSetAttribute(hgemm<false,1>, cudaFuncAttributeMaxDynamicSharedMemorySize, SMEM_DYN);
  cudaFuncSetAttribute(hgemm<false,4>, cudaFuncAttributeMaxDynamicSharedMemorySize, SMEM_DYN);
  const long long sQ=(long long)NSEQ*QKVW, sKV=(long long)DIM*DIM, sA=(long long)NSEQ*DIM;

  split_kernel<<<(MTOT*(size_t)DIM)/1024, 256>>>(x, xh, xl);
  split_kernel<<<((size_t)QKVW*DIM)/1024, 256>>>(Wqkv, wqh, wql);
  split_kernel<<<((size_t)DIM*DIM)/1024, 256>>>(Wout, woh, wol);
  // 1) qkv = x @ Wqkv^T, relu+eps on q,k  -> planes
  hgemm<false,0><<<dim3(QKVW/256, MTOT/128, 1),256,SMEM_DYN>>>(
      xh, xl, DIM,0, wqh, wql, DIM,0, DIM, qkvh, qkvl, nullptr, QKVW,0, nullptr,0, nullptr);
  // 2) ksum
  ksum_zero<<<32,256>>>(ksum);
  ksum_kernel<<<dim3(DIM/256,BATCH,8),256>>>(qkvh, qkvl, ksum);
  // 3) kv[b,d,e] = sum_n K[n,d]V[n,e]  (TRANS; A=K -> M=d, B=V -> N=e) -> planes
  hgemm<true,1><<<dim3(DIM/256, DIM/128, BATCH),256,SMEM_DYN>>>(
      qkvh+DIM, qkvl+DIM, QKVW, sQ, qkvh+2*DIM, qkvl+2*DIM, QKVW, sQ, NSEQ,
      kvh, kvl, nullptr, DIM, sKV, nullptr,0, nullptr);
  // 4) z
  z_kernel<<<MTOT/8,256>>>(qkvh, qkvl, ksum, z);
  // 5) P[b,f,d] = sum_e Wout[f,e]*kv[b,d,e]  (NT: A=Wout, B=kv) -> planes
  hgemm<false,1><<<dim3(DIM/256, DIM/128, BATCH),256,SMEM_DYN>>>(
      woh, wol, DIM,0, kvh, kvl, DIM, sKV, DIM,
      ph, pl, nullptr, DIM, sKV, nullptr,0, nullptr);
  // 6) out[n,f] = z[n]*sum_d Q[n,d]*P[f,d] + b[f]  (NT: A=Q, B=P; EPI=4) -> fp32
  hgemm<false,4><<<dim3(DIM/256, NSEQ/128, BATCH),256,SMEM_DYN>>>(
      qkvh, qkvl, QKVW, sQ, ph, pl, DIM, sKV, DIM,
      nullptr, nullptr, out, DIM, sA, z, NSEQ, bout);
}